// round 10
// baseline (speedup 1.0000x reference)
#include <cuda_runtime.h>
#include <cuda_fp16.h>
#include <math.h>
#include <stdint.h>

// ---------------- problem constants ----------------
#define TOK    8192
#define DD     2048
#define NE     64
#define KSPL   4          // K-split -> grid (64, 4)
#define DSPL   512        // d per split
#define BM     128        // tokens per CTA
#define CHUNK  64         // k per chunk
#define NCHK   (DSPL / CHUNK)   // 8 chunks
#define NPROB  16384
#define LSCALE 2048.0f    // 2^11 residual scale
#define LINV   (1.0f / 2048.0f)

// partial scores [KSPL][TOK][NE] = 8 MB
__device__ float g_part[KSPL * TOK * NE];
// W transposed + 2-level fp16 split (l pre-scaled by 2^11): [expert n][feature k]
__device__ __half g_Wh[NE * 2 * DD];
__device__ __half g_Wl[NE * 2 * DD];

// ---------------- helpers ----------------
__device__ __forceinline__ uint32_t smem_u32(const void* p) {
    uint32_t a;
    asm("{ .reg .u64 t; cvta.to.shared.u64 t, %1; cvt.u32.u64 %0, t; }" : "=r"(a) : "l"(p));
    return a;
}
__device__ __forceinline__ uint32_t packh2(__half x, __half y) {
    __half2 v = __halves2half2(x, y);
    return *reinterpret_cast<uint32_t*>(&v);
}
// 2-level fp16 split of a float pair; l scaled by 2^11
__device__ __forceinline__ void split2h(float x, float y, uint32_t& h, uint32_t& l) {
    const __half hx = __float2half_rn(x);
    const __half hy = __float2half_rn(y);
    const float rx = (x - __half2float(hx)) * LSCALE;
    const float ry = (y - __half2float(hy)) * LSCALE;
    h = packh2(hx, hy);
    l = packh2(__float2half_rn(rx), __float2half_rn(ry));
}
__device__ __forceinline__ void mma16816(float* c, const uint32_t* a, const uint32_t* b) {
    asm volatile(
        "mma.sync.aligned.m16n8k16.row.col.f32.f16.f16.f32 "
        "{%0,%1,%2,%3}, {%4,%5,%6,%7}, {%8,%9}, {%0,%1,%2,%3};"
        : "+f"(c[0]), "+f"(c[1]), "+f"(c[2]), "+f"(c[3])
        : "r"(a[0]), "r"(a[1]), "r"(a[2]), "r"(a[3]), "r"(b[0]), "r"(b[1]));
}
__device__ __forceinline__ void ldsm4(uint32_t* r, uint32_t addr) {
    asm volatile("ldmatrix.sync.aligned.m8n8.x4.shared.b16 {%0,%1,%2,%3}, [%4];"
                 : "=r"(r[0]), "=r"(r[1]), "=r"(r[2]), "=r"(r[3]) : "r"(addr));
}
__device__ __forceinline__ void stsh128(uint32_t addr, uint4 v) {
    asm volatile("st.shared.v4.b32 [%0], {%1, %2, %3, %4};"
                 :: "r"(addr), "r"(v.x), "r"(v.y), "r"(v.z), "r"(v.w) : "memory");
}

// ---------------- setup: transpose + 2-level fp16-split W ----------------
// 256 CTAs, each transposes a 16k x 64n tile (latency-parallel).
__global__ __launch_bounds__(256)
void wsplit_kernel(const float* __restrict__ W) {
    __shared__ float tile[16][65];
    const int k0  = blockIdx.x * 16;
    const int tid = threadIdx.x;
    {
        const int r  = tid >> 4;          // 0..15
        const int c4 = (tid & 15) * 4;    // 0..60
        const float4 v = *(const float4*)&W[(size_t)(k0 + r) * NE + c4];
        tile[r][c4]     = v.x;
        tile[r][c4 + 1] = v.y;
        tile[r][c4 + 2] = v.z;
        tile[r][c4 + 3] = v.w;
    }
    __syncthreads();
    const int n  = tid >> 2;          // 0..63
    const int ks = (tid & 3) * 4;     // 0,4,8,12
    union { __half h[4]; uint2 q; } hb, lb;
#pragma unroll
    for (int kk = 0; kk < 4; kk++) {
        const float v = tile[ks + kk][n];
        const __half h = __float2half_rn(v);
        hb.h[kk] = h;
        lb.h[kk] = __float2half_rn((v - __half2float(h)) * LSCALE);
    }
    const size_t idx = (size_t)n * (2 * DD) + k0 + ks;
    *(uint2*)(g_Wh + idx) = hb.q;
    *(uint2*)(g_Wl + idx) = lb.q;
}

// ---------------- main: fused amp/phase + 2-level fp16 split mma GEMM ----------------
// 8 warps, each owns m16 (16 tokens) x n64. A frags built in registers.
// x loads software-pipelined one kt ahead so DRAM latency hides under MMAs.
__global__ __launch_bounds__(256, 2)
void gemm_mma_kernel(const float* __restrict__ xr, const float* __restrict__ xi) {
    // W tiles: 4 arrays [Wa_h, Wa_l, Wp_h, Wp_l], 64n x 64k fp16, swizzled
    __shared__ __align__(128) uint8_t sW[4 * 8192];
    const uint32_t swb = smem_u32(sW);

    const int tid  = threadIdx.x;
    const int w    = tid >> 5;
    const int lane = tid & 31;
    const int qr   = lane >> 2;          // frag row 0..7
    const int qc   = (lane & 3) * 2;     // frag col pair
    const int tok0 = blockIdx.x * BM;
    const int ks   = blockIdx.y;

    // ldmatrix lane-address constants
    const uint32_t ldrow = ((lane >> 4) << 3) + (lane & 7);     // 0..15
    const uint32_t kboff = ((lane >> 3) & 1) * 16;              // 0 / 16 bytes
    const uint32_t kxor  = (lane & 7) << 4;                     // swizzle XOR

    float accm[8][4], accc[8][4];
#pragma unroll
    for (int nt = 0; nt < 8; nt++)
#pragma unroll
        for (int j = 0; j < 4; j++) { accm[nt][j] = 0.0f; accc[nt][j] = 0.0f; }

    const int rA = tok0 + w * 16 + qr;         // token row (and +8)
    const size_t rowbase = (size_t)rA * DD + qc;

    for (int c = 0; c < NCHK; c++) {
        const int koff = ks * DSPL + c * CHUNK;
        __syncthreads();
        // ---- stage W: 4 arrays, each thread moves 32B per array (swizzled smem)
        {
            const int n  = tid >> 2;
            const int ke = (tid & 3) * 16;
            const size_t gA = (size_t)n * (2 * DD) + koff + ke;
            const size_t gP = gA + DD;
            const uint32_t row = (uint32_t)n * 128;
            const uint32_t xv  = (uint32_t)(n & 7) << 4;
            const uint32_t c0  = row + (((uint32_t)(ke * 2)) ^ xv);
            const uint32_t c1  = row + (((uint32_t)(ke * 2 + 16)) ^ xv);
            uint4 v;
            v = *(const uint4*)(g_Wh + gA);     stsh128(swb + 0 * 8192 + c0, v);
            v = *(const uint4*)(g_Wh + gA + 8); stsh128(swb + 0 * 8192 + c1, v);
            v = *(const uint4*)(g_Wl + gA);     stsh128(swb + 1 * 8192 + c0, v);
            v = *(const uint4*)(g_Wl + gA + 8); stsh128(swb + 1 * 8192 + c1, v);
            v = *(const uint4*)(g_Wh + gP);     stsh128(swb + 2 * 8192 + c0, v);
            v = *(const uint4*)(g_Wh + gP + 8); stsh128(swb + 2 * 8192 + c1, v);
            v = *(const uint4*)(g_Wl + gP);     stsh128(swb + 3 * 8192 + c0, v);
            v = *(const uint4*)(g_Wl + gP + 8); stsh128(swb + 3 * 8192 + c1, v);
        }
        __syncthreads();

        // ---- prefetch x for kt=0
        float2 prR[4], prI[4], prR2[4], prI2[4];
        {
            const size_t b0 = rowbase + koff;           // kt 0
            const size_t b1 = b0 + (size_t)8 * DD;
            prR[0] = *(const float2*)(xr + b0);
            prR[1] = *(const float2*)(xr + b0 + 8);
            prR[2] = *(const float2*)(xr + b1);
            prR[3] = *(const float2*)(xr + b1 + 8);
            prI[0] = *(const float2*)(xi + b0);
            prI[1] = *(const float2*)(xi + b0 + 8);
            prI[2] = *(const float2*)(xi + b1);
            prI[3] = *(const float2*)(xi + b1 + 8);
        }

#pragma unroll
        for (int kt = 0; kt < 4; kt++) {
            // ---- consume current, issue next kt's loads first (latency hiding)
            const float2 r00 = prR[0], r02 = prR[1], r10 = prR[2], r12 = prR[3];
            const float2 i00 = prI[0], i02 = prI[1], i10 = prI[2], i12 = prI[3];
            if (kt < 3) {
                const size_t b0 = rowbase + koff + (kt + 1) * 16;
                const size_t b1 = b0 + (size_t)8 * DD;
                prR2[0] = *(const float2*)(xr + b0);
                prR2[1] = *(const float2*)(xr + b0 + 8);
                prR2[2] = *(const float2*)(xr + b1);
                prR2[3] = *(const float2*)(xr + b1 + 8);
                prI2[0] = *(const float2*)(xi + b0);
                prI2[1] = *(const float2*)(xi + b0 + 8);
                prI2[2] = *(const float2*)(xi + b1);
                prI2[3] = *(const float2*)(xi + b1 + 8);
            }

            // ---- amp / phase (8 elems)
            const float a00 = sqrtf(fmaf(r00.x, r00.x, i00.x * i00.x)), p00 = atan2f(i00.x, r00.x);
            const float a01 = sqrtf(fmaf(r00.y, r00.y, i00.y * i00.y)), p01 = atan2f(i00.y, r00.y);
            const float a10 = sqrtf(fmaf(r10.x, r10.x, i10.x * i10.x)), p10 = atan2f(i10.x, r10.x);
            const float a11 = sqrtf(fmaf(r10.y, r10.y, i10.y * i10.y)), p11 = atan2f(i10.y, r10.y);
            const float a02 = sqrtf(fmaf(r02.x, r02.x, i02.x * i02.x)), p02 = atan2f(i02.x, r02.x);
            const float a03 = sqrtf(fmaf(r02.y, r02.y, i02.y * i02.y)), p03 = atan2f(i02.y, r02.y);
            const float a12 = sqrtf(fmaf(r12.x, r12.x, i12.x * i12.x)), p12 = atan2f(i12.x, r12.x);
            const float a13 = sqrtf(fmaf(r12.y, r12.y, i12.y * i12.y)), p13 = atan2f(i12.y, r12.y);

            // ---- 2-level fp16 split into A-fragment layout (l scaled 2^11)
            uint32_t Ah[4], Al[4], Ph[4], Pl[4];
            split2h(a00, a01, Ah[0], Al[0]);
            split2h(a10, a11, Ah[1], Al[1]);
            split2h(a02, a03, Ah[2], Al[2]);
            split2h(a12, a13, Ah[3], Al[3]);
            split2h(p00, p01, Ph[0], Pl[0]);
            split2h(p10, p11, Ph[1], Pl[1]);
            split2h(p02, p03, Ph[2], Pl[2]);
            split2h(p12, p13, Ph[3], Pl[3]);

            const uint32_t kb = ((uint32_t)(kt * 32) + kboff) ^ kxor;
            uint32_t wreg[16];

            // ---- amp Wh: main Ah*Wh, corr Al'*Wh
#pragma unroll
            for (int g = 0; g < 4; g++)
                ldsm4(&wreg[g * 4], swb + 0 * 8192 + (g * 16 + ldrow) * 128 + kb);
#pragma unroll
            for (int nt = 0; nt < 8; nt++) {
                mma16816(accm[nt], Ah, &wreg[nt * 2]);
                mma16816(accc[nt], Al, &wreg[nt * 2]);
            }
            // ---- amp Wl': corr Ah*Wl'
#pragma unroll
            for (int g = 0; g < 4; g++)
                ldsm4(&wreg[g * 4], swb + 1 * 8192 + (g * 16 + ldrow) * 128 + kb);
#pragma unroll
            for (int nt = 0; nt < 8; nt++)
                mma16816(accc[nt], Ah, &wreg[nt * 2]);

            // ---- phase Wh: main Ph*Wh, corr Pl'*Wh
#pragma unroll
            for (int g = 0; g < 4; g++)
                ldsm4(&wreg[g * 4], swb + 2 * 8192 + (g * 16 + ldrow) * 128 + kb);
#pragma unroll
            for (int nt = 0; nt < 8; nt++) {
                mma16816(accm[nt], Ph, &wreg[nt * 2]);
                mma16816(accc[nt], Pl, &wreg[nt * 2]);
            }
            // ---- phase Wl': corr Ph*Wl'
#pragma unroll
            for (int g = 0; g < 4; g++)
                ldsm4(&wreg[g * 4], swb + 3 * 8192 + (g * 16 + ldrow) * 128 + kb);
#pragma unroll
            for (int nt = 0; nt < 8; nt++)
                mma16816(accc[nt], Ph, &wreg[nt * 2]);

            // ---- rotate prefetch buffers
            if (kt < 3) {
#pragma unroll
                for (int u = 0; u < 4; u++) { prR[u] = prR2[u]; prI[u] = prI2[u]; }
            }
        }
    }

    // ---- epilogue: combine main + corr/2048, store to partials
    float* dst0 = g_part + ((size_t)ks * TOK + rA) * NE;
    float* dst1 = dst0 + (size_t)8 * NE;
#pragma unroll
    for (int nt = 0; nt < 8; nt++) {
        const float v0 = fmaf(accc[nt][0], LINV, accm[nt][0]);
        const float v1 = fmaf(accc[nt][1], LINV, accm[nt][1]);
        const float v2 = fmaf(accc[nt][2], LINV, accm[nt][2]);
        const float v3 = fmaf(accc[nt][3], LINV, accm[nt][3]);
        *(float2*)&dst0[nt * 8 + qc] = make_float2(v0, v1);
        *(float2*)&dst1[nt * 8 + qc] = make_float2(v2, v3);
    }
}

// ---------------- reduce + top-2 + renormalized softmax ----------------
__global__ __launch_bounds__(256)
void topk_kernel(const float* __restrict__ bvec, float* __restrict__ out) {
    const int gtid = blockIdx.x * blockDim.x + threadIdx.x;
    const int tok  = gtid >> 5;
    const int lane = threadIdx.x & 31;
    if (tok >= TOK) return;

    float s0 = 0.0f, s1 = 0.0f;
#pragma unroll
    for (int ks = 0; ks < KSPL; ks++) {
        const float2 v = *(const float2*)&g_part[((size_t)ks * TOK + tok) * NE + lane * 2];
        s0 += v.x; s1 += v.y;
    }
    s0 += bvec[2 * lane];
    s1 += bvec[2 * lane + 1];

    // top-1, jax tie-break (lower index wins on equal)
    float bv; int bi;
    if (s1 > s0) { bv = s1; bi = 2 * lane + 1; } else { bv = s0; bi = 2 * lane; }
#pragma unroll
    for (int off = 16; off > 0; off >>= 1) {
        const float ov = __shfl_down_sync(0xffffffffu, bv, off);
        const int   oi = __shfl_down_sync(0xffffffffu, bi, off);
        if (ov > bv || (ov == bv && oi < bi)) { bv = ov; bi = oi; }
    }
    bv = __shfl_sync(0xffffffffu, bv, 0);
    bi = __shfl_sync(0xffffffffu, bi, 0);

    const float NEG = -3.4e38f;
    float t0 = (2 * lane     == bi) ? NEG : s0;
    float t1 = (2 * lane + 1 == bi) ? NEG : s1;
    float cv; int ci;
    if (t1 > t0) { cv = t1; ci = 2 * lane + 1; } else { cv = t0; ci = 2 * lane; }
#pragma unroll
    for (int off = 16; off > 0; off >>= 1) {
        const float ov = __shfl_down_sync(0xffffffffu, cv, off);
        const int   oi = __shfl_down_sync(0xffffffffu, ci, off);
        if (ov > cv || (ov == cv && oi < ci)) { cv = ov; ci = oi; }
    }

    if (lane == 0) {
        // renormalized top-2 softmax: global denominator cancels, max = bv
        const float r  = expf(cv - bv);
        const float dn = 1.0f + r;
        out[tok * 2]             = 1.0f / dn;
        out[tok * 2 + 1]         = r / dn;
        out[NPROB + tok * 2]     = (float)bi;
        out[NPROB + tok * 2 + 1] = (float)ci;
    }
}

extern "C" void kernel_launch(void* const* d_in, const int* in_sizes, int n_in,
                              void* d_out, int out_size) {
    const float* xr = (const float*)d_in[0];   // x_real [4,2048,2048]
    const float* xi = (const float*)d_in[1];   // x_imag [4,2048,2048]
    const float* W  = (const float*)d_in[2];   // [4096, 64]
    const float* b  = (const float*)d_in[3];   // [64]
    float* out = (float*)d_out;                // [16384 probs][16384 indices]

    wsplit_kernel<<<2 * DD / 16, 256>>>(W);
    dim3 grid(TOK / BM, KSPL);
    gemm_mma_kernel<<<grid, 256>>>(xr, xi);
    topk_kernel<<<TOK * 32 / 256, 256>>>(b, out);
}

// round 11
// speedup vs baseline: 1.1386x; 1.1386x over previous
#include <cuda_runtime.h>
#include <cuda_fp16.h>
#include <math.h>
#include <stdint.h>

// ---------------- problem constants ----------------
#define TOK    8192
#define DD     2048
#define NE     64
#define KSPL   4          // K-split -> grid (64, 4)
#define DSPL   512        // d per split
#define BM     128        // tokens per CTA
#define CHUNK  64         // k per chunk
#define NCHK   (DSPL / CHUNK)   // 8 chunks
#define NQ     (NCHK * 4)       // 32 kt-steps total per CTA
#define NPROB  16384
#define LSCALE 2048.0f    // 2^11 residual scale
#define LINV   (1.0f / 2048.0f)

// SMEM layout (dynamic): [0,32K) W tiles, [32K, 96K) x staging 4 bufs x 16KB
#define SM_W   0
#define SM_X   32768
#define XBUF   16384
#define SMEM_TOTAL (32768 + 4 * XBUF)

// partial scores [KSPL][TOK][NE] = 8 MB
__device__ float g_part[KSPL * TOK * NE];
// W transposed + 2-level fp16 split (l pre-scaled by 2^11): [expert n][feature k]
__device__ __half g_Wh[NE * 2 * DD];
__device__ __half g_Wl[NE * 2 * DD];

// ---------------- helpers ----------------
__device__ __forceinline__ uint32_t smem_u32(const void* p) {
    uint32_t a;
    asm("{ .reg .u64 t; cvta.to.shared.u64 t, %1; cvt.u32.u64 %0, t; }" : "=r"(a) : "l"(p));
    return a;
}
__device__ __forceinline__ uint32_t packh2(__half x, __half y) {
    __half2 v = __halves2half2(x, y);
    return *reinterpret_cast<uint32_t*>(&v);
}
// 2-level fp16 split of a float pair; l scaled by 2^11
__device__ __forceinline__ void split2h(float x, float y, uint32_t& h, uint32_t& l) {
    const __half hx = __float2half_rn(x);
    const __half hy = __float2half_rn(y);
    const float rx = (x - __half2float(hx)) * LSCALE;
    const float ry = (y - __half2float(hy)) * LSCALE;
    h = packh2(hx, hy);
    l = packh2(__float2half_rn(rx), __float2half_rn(ry));
}
__device__ __forceinline__ void mma16816(float* c, const uint32_t* a, const uint32_t* b) {
    asm volatile(
        "mma.sync.aligned.m16n8k16.row.col.f32.f16.f16.f32 "
        "{%0,%1,%2,%3}, {%4,%5,%6,%7}, {%8,%9}, {%0,%1,%2,%3};"
        : "+f"(c[0]), "+f"(c[1]), "+f"(c[2]), "+f"(c[3])
        : "r"(a[0]), "r"(a[1]), "r"(a[2]), "r"(a[3]), "r"(b[0]), "r"(b[1]));
}
__device__ __forceinline__ void ldsm4(uint32_t* r, uint32_t addr) {
    asm volatile("ldmatrix.sync.aligned.m8n8.x4.shared.b16 {%0,%1,%2,%3}, [%4];"
                 : "=r"(r[0]), "=r"(r[1]), "=r"(r[2]), "=r"(r[3]) : "r"(addr));
}
__device__ __forceinline__ void stsh128(uint32_t addr, uint4 v) {
    asm volatile("st.shared.v4.b32 [%0], {%1, %2, %3, %4};"
                 :: "r"(addr), "r"(v.x), "r"(v.y), "r"(v.z), "r"(v.w) : "memory");
}
__device__ __forceinline__ void cpa8(uint32_t dst, const float* src) {
    asm volatile("cp.async.ca.shared.global [%0], [%1], 8;" :: "r"(dst), "l"(src) : "memory");
}
__device__ __forceinline__ void cpa_commit() {
    asm volatile("cp.async.commit_group;" ::: "memory");
}
__device__ __forceinline__ float2 ldsf2(uint32_t a) {
    float2 v;
    asm volatile("ld.shared.v2.f32 {%0,%1}, [%2];" : "=f"(v.x), "=f"(v.y) : "r"(a));
    return v;
}

// ---------------- setup: transpose + 2-level fp16-split W ----------------
// 256 CTAs, each transposes a 16k x 64n tile (latency-parallel).
__global__ __launch_bounds__(256)
void wsplit_kernel(const float* __restrict__ W) {
    __shared__ float tile[16][65];
    const int k0  = blockIdx.x * 16;
    const int tid = threadIdx.x;
    {
        const int r  = tid >> 4;          // 0..15
        const int c4 = (tid & 15) * 4;    // 0..60
        const float4 v = *(const float4*)&W[(size_t)(k0 + r) * NE + c4];
        tile[r][c4]     = v.x;
        tile[r][c4 + 1] = v.y;
        tile[r][c4 + 2] = v.z;
        tile[r][c4 + 3] = v.w;
    }
    __syncthreads();
    const int n  = tid >> 2;          // 0..63
    const int ks = (tid & 3) * 4;     // 0,4,8,12
    union { __half h[4]; uint2 q; } hb, lb;
#pragma unroll
    for (int kk = 0; kk < 4; kk++) {
        const float v = tile[ks + kk][n];
        const __half h = __float2half_rn(v);
        hb.h[kk] = h;
        lb.h[kk] = __float2half_rn((v - __half2float(h)) * LSCALE);
    }
    const size_t idx = (size_t)n * (2 * DD) + k0 + ks;
    *(uint2*)(g_Wh + idx) = hb.q;
    *(uint2*)(g_Wl + idx) = lb.q;
}

// ---------------- main: fused amp/phase + 2-level fp16 split mma GEMM ----------------
// 8 warps, each owns m16 (16 tokens) x n64. A frags built in registers.
// x staged through smem via per-thread cp.async (zero register cost, no barriers:
// each thread consumes only its own staged data). 4 buffers -> reuse distance 4.
__global__ __launch_bounds__(256, 2)
void gemm_mma_kernel(const float* __restrict__ xr, const float* __restrict__ xi) {
    extern __shared__ __align__(128) uint8_t smem[];
    const uint32_t swb = smem_u32(smem);          // W tiles at swb + SM_W
    const uint32_t sxb = swb + SM_X;              // x staging

    const int tid  = threadIdx.x;
    const int w    = tid >> 5;
    const int lane = tid & 31;
    const int qr   = lane >> 2;          // frag row 0..7
    const int qc   = (lane & 3) * 2;     // frag col pair
    const int tok0 = blockIdx.x * BM;
    const int ks   = blockIdx.y;

    // ldmatrix lane-address constants
    const uint32_t ldrow = ((lane >> 4) << 3) + (lane & 7);     // 0..15
    const uint32_t kboff = ((lane >> 3) & 1) * 16;              // 0 / 16 bytes
    const uint32_t kxor  = (lane & 7) << 4;                     // swizzle XOR

    float accm[8][4], accc[8][4];
#pragma unroll
    for (int nt = 0; nt < 8; nt++)
#pragma unroll
        for (int j = 0; j < 4; j++) { accm[nt][j] = 0.0f; accc[nt][j] = 0.0f; }

    const int rA = tok0 + w * 16 + qr;         // token row (and +8)
    const size_t rowbase = (size_t)rA * DD + qc + (size_t)ks * DSPL;
    const uint32_t sxt = sxb + (uint32_t)tid * 8;

    // issue kt-step q's 8 cp.async pieces into buffer q&3, as one group
    auto issue_q = [&](int q) {
        const uint32_t base = sxt + (uint32_t)(q & 3) * XBUF;
        const size_t b0 = rowbase + (size_t)q * 16;
        const size_t b1 = b0 + (size_t)8 * DD;
        cpa8(base + 0 * 2048, xr + b0);
        cpa8(base + 1 * 2048, xr + b0 + 8);
        cpa8(base + 2 * 2048, xr + b1);
        cpa8(base + 3 * 2048, xr + b1 + 8);
        cpa8(base + 4 * 2048, xi + b0);
        cpa8(base + 5 * 2048, xi + b0 + 8);
        cpa8(base + 6 * 2048, xi + b1);
        cpa8(base + 7 * 2048, xi + b1 + 8);
        cpa_commit();
    };

    // prologue: get 2 kt-steps in flight
    issue_q(0);
    issue_q(1);

    for (int c = 0; c < NCHK; c++) {
        const int koff = ks * DSPL + c * CHUNK;
        __syncthreads();
        // ---- stage W: 4 arrays, each thread moves 32B per array (swizzled smem)
        {
            const int n  = tid >> 2;
            const int ke = (tid & 3) * 16;
            const size_t gA = (size_t)n * (2 * DD) + koff + ke;
            const size_t gP = gA + DD;
            const uint32_t row = (uint32_t)n * 128;
            const uint32_t xv  = (uint32_t)(n & 7) << 4;
            const uint32_t c0  = row + (((uint32_t)(ke * 2)) ^ xv);
            const uint32_t c1  = row + (((uint32_t)(ke * 2 + 16)) ^ xv);
            uint4 v;
            v = *(const uint4*)(g_Wh + gA);     stsh128(swb + 0 * 8192 + c0, v);
            v = *(const uint4*)(g_Wh + gA + 8); stsh128(swb + 0 * 8192 + c1, v);
            v = *(const uint4*)(g_Wl + gA);     stsh128(swb + 1 * 8192 + c0, v);
            v = *(const uint4*)(g_Wl + gA + 8); stsh128(swb + 1 * 8192 + c1, v);
            v = *(const uint4*)(g_Wh + gP);     stsh128(swb + 2 * 8192 + c0, v);
            v = *(const uint4*)(g_Wh + gP + 8); stsh128(swb + 2 * 8192 + c1, v);
            v = *(const uint4*)(g_Wl + gP);     stsh128(swb + 3 * 8192 + c0, v);
            v = *(const uint4*)(g_Wl + gP + 8); stsh128(swb + 3 * 8192 + c1, v);
        }
        __syncthreads();

#pragma unroll
        for (int kt = 0; kt < 4; kt++) {
            const int q = c * 4 + kt;
            // ---- keep 2 kt-steps in flight
            if (q + 2 < NQ) issue_q(q + 2);
            // ---- wait for q's group (2 newer groups may be pending)
            if (q + 2 < NQ) {
                asm volatile("cp.async.wait_group 2;" ::: "memory");
            } else if (q + 1 < NQ) {
                asm volatile("cp.async.wait_group 1;" ::: "memory");
            } else {
                asm volatile("cp.async.wait_group 0;" ::: "memory");
            }

            // ---- read q's x from own staging slot (no barrier needed)
            const uint32_t rb = sxt + (uint32_t)(q & 3) * XBUF;
            const float2 r00 = ldsf2(rb + 0 * 2048);
            const float2 r02 = ldsf2(rb + 1 * 2048);
            const float2 r10 = ldsf2(rb + 2 * 2048);
            const float2 r12 = ldsf2(rb + 3 * 2048);
            const float2 i00 = ldsf2(rb + 4 * 2048);
            const float2 i02 = ldsf2(rb + 5 * 2048);
            const float2 i10 = ldsf2(rb + 6 * 2048);
            const float2 i12 = ldsf2(rb + 7 * 2048);

            // ---- amp / phase (8 elems)
            const float a00 = sqrtf(fmaf(r00.x, r00.x, i00.x * i00.x)), p00 = atan2f(i00.x, r00.x);
            const float a01 = sqrtf(fmaf(r00.y, r00.y, i00.y * i00.y)), p01 = atan2f(i00.y, r00.y);
            const float a10 = sqrtf(fmaf(r10.x, r10.x, i10.x * i10.x)), p10 = atan2f(i10.x, r10.x);
            const float a11 = sqrtf(fmaf(r10.y, r10.y, i10.y * i10.y)), p11 = atan2f(i10.y, r10.y);
            const float a02 = sqrtf(fmaf(r02.x, r02.x, i02.x * i02.x)), p02 = atan2f(i02.x, r02.x);
            const float a03 = sqrtf(fmaf(r02.y, r02.y, i02.y * i02.y)), p03 = atan2f(i02.y, r02.y);
            const float a12 = sqrtf(fmaf(r12.x, r12.x, i12.x * i12.x)), p12 = atan2f(i12.x, r12.x);
            const float a13 = sqrtf(fmaf(r12.y, r12.y, i12.y * i12.y)), p13 = atan2f(i12.y, r12.y);

            // ---- 2-level fp16 split into A-fragment layout (l scaled 2^11)
            uint32_t Ah[4], Al[4], Ph[4], Pl[4];
            split2h(a00, a01, Ah[0], Al[0]);
            split2h(a10, a11, Ah[1], Al[1]);
            split2h(a02, a03, Ah[2], Al[2]);
            split2h(a12, a13, Ah[3], Al[3]);
            split2h(p00, p01, Ph[0], Pl[0]);
            split2h(p10, p11, Ph[1], Pl[1]);
            split2h(p02, p03, Ph[2], Pl[2]);
            split2h(p12, p13, Ph[3], Pl[3]);

            const uint32_t kb = ((uint32_t)(kt * 32) + kboff) ^ kxor;
            uint32_t wreg[16];

            // ---- amp Wh: main Ah*Wh, corr Al'*Wh
#pragma unroll
            for (int g = 0; g < 4; g++)
                ldsm4(&wreg[g * 4], swb + 0 * 8192 + (g * 16 + ldrow) * 128 + kb);
#pragma unroll
            for (int nt = 0; nt < 8; nt++) {
                mma16816(accm[nt], Ah, &wreg[nt * 2]);
                mma16816(accc[nt], Al, &wreg[nt * 2]);
            }
            // ---- amp Wl': corr Ah*Wl'
#pragma unroll
            for (int g = 0; g < 4; g++)
                ldsm4(&wreg[g * 4], swb + 1 * 8192 + (g * 16 + ldrow) * 128 + kb);
#pragma unroll
            for (int nt = 0; nt < 8; nt++)
                mma16816(accc[nt], Ah, &wreg[nt * 2]);

            // ---- phase Wh: main Ph*Wh, corr Pl'*Wh
#pragma unroll
            for (int g = 0; g < 4; g++)
                ldsm4(&wreg[g * 4], swb + 2 * 8192 + (g * 16 + ldrow) * 128 + kb);
#pragma unroll
            for (int nt = 0; nt < 8; nt++) {
                mma16816(accm[nt], Ph, &wreg[nt * 2]);
                mma16816(accc[nt], Pl, &wreg[nt * 2]);
            }
            // ---- phase Wl': corr Ph*Wl'
#pragma unroll
            for (int g = 0; g < 4; g++)
                ldsm4(&wreg[g * 4], swb + 3 * 8192 + (g * 16 + ldrow) * 128 + kb);
#pragma unroll
            for (int nt = 0; nt < 8; nt++)
                mma16816(accc[nt], Ph, &wreg[nt * 2]);
        }
    }

    // ---- epilogue: combine main + corr/2048, store to partials
    float* dst0 = g_part + ((size_t)ks * TOK + rA) * NE;
    float* dst1 = dst0 + (size_t)8 * NE;
#pragma unroll
    for (int nt = 0; nt < 8; nt++) {
        const float v0 = fmaf(accc[nt][0], LINV, accm[nt][0]);
        const float v1 = fmaf(accc[nt][1], LINV, accm[nt][1]);
        const float v2 = fmaf(accc[nt][2], LINV, accm[nt][2]);
        const float v3 = fmaf(accc[nt][3], LINV, accm[nt][3]);
        *(float2*)&dst0[nt * 8 + qc] = make_float2(v0, v1);
        *(float2*)&dst1[nt * 8 + qc] = make_float2(v2, v3);
    }
}

// ---------------- reduce + top-2 + renormalized softmax ----------------
__global__ __launch_bounds__(256)
void topk_kernel(const float* __restrict__ bvec, float* __restrict__ out) {
    const int gtid = blockIdx.x * blockDim.x + threadIdx.x;
    const int tok  = gtid >> 5;
    const int lane = threadIdx.x & 31;
    if (tok >= TOK) return;

    float s0 = 0.0f, s1 = 0.0f;
#pragma unroll
    for (int ks = 0; ks < KSPL; ks++) {
        const float2 v = *(const float2*)&g_part[((size_t)ks * TOK + tok) * NE + lane * 2];
        s0 += v.x; s1 += v.y;
    }
    s0 += bvec[2 * lane];
    s1 += bvec[2 * lane + 1];

    // top-1, jax tie-break (lower index wins on equal)
    float bv; int bi;
    if (s1 > s0) { bv = s1; bi = 2 * lane + 1; } else { bv = s0; bi = 2 * lane; }
#pragma unroll
    for (int off = 16; off > 0; off >>= 1) {
        const float ov = __shfl_down_sync(0xffffffffu, bv, off);
        const int   oi = __shfl_down_sync(0xffffffffu, bi, off);
        if (ov > bv || (ov == bv && oi < bi)) { bv = ov; bi = oi; }
    }
    bv = __shfl_sync(0xffffffffu, bv, 0);
    bi = __shfl_sync(0xffffffffu, bi, 0);

    const float NEG = -3.4e38f;
    float t0 = (2 * lane     == bi) ? NEG : s0;
    float t1 = (2 * lane + 1 == bi) ? NEG : s1;
    float cv; int ci;
    if (t1 > t0) { cv = t1; ci = 2 * lane + 1; } else { cv = t0; ci = 2 * lane; }
#pragma unroll
    for (int off = 16; off > 0; off >>= 1) {
        const float ov = __shfl_down_sync(0xffffffffu, cv, off);
        const int   oi = __shfl_down_sync(0xffffffffu, ci, off);
        if (ov > cv || (ov == cv && oi < ci)) { cv = ov; ci = oi; }
    }

    if (lane == 0) {
        // renormalized top-2 softmax: global denominator cancels, max = bv
        const float r  = expf(cv - bv);
        const float dn = 1.0f + r;
        out[tok * 2]             = 1.0f / dn;
        out[tok * 2 + 1]         = r / dn;
        out[NPROB + tok * 2]     = (float)bi;
        out[NPROB + tok * 2 + 1] = (float)ci;
    }
}

extern "C" void kernel_launch(void* const* d_in, const int* in_sizes, int n_in,
                              void* d_out, int out_size) {
    const float* xr = (const float*)d_in[0];   // x_real [4,2048,2048]
    const float* xi = (const float*)d_in[1];   // x_imag [4,2048,2048]
    const float* W  = (const float*)d_in[2];   // [4096, 64]
    const float* b  = (const float*)d_in[3];   // [64]
    float* out = (float*)d_out;                // [16384 probs][16384 indices]

    cudaFuncSetAttribute(gemm_mma_kernel, cudaFuncAttributeMaxDynamicSharedMemorySize, SMEM_TOTAL);

    wsplit_kernel<<<2 * DD / 16, 256>>>(W);
    dim3 grid(TOK / BM, KSPL);
    gemm_mma_kernel<<<grid, 256, SMEM_TOTAL>>>(xr, xi);
    topk_kernel<<<TOK * 32 / 256, 256>>>(b, out);
}

// round 12
// speedup vs baseline: 1.2568x; 1.1038x over previous
#include <cuda_runtime.h>
#include <cuda_fp16.h>
#include <math.h>
#include <stdint.h>

// ---------------- problem constants ----------------
#define TOK    8192
#define DD     2048
#define NE     64
#define KSPL   16         // K-split -> grid (64, 16) = 1024 CTAs (98.9% balance @ occ 2)
#define DSPL   128        // d per split
#define BM     128        // tokens per CTA
#define CHUNK  64         // k per chunk
#define NCHK   (DSPL / CHUNK)   // 2 chunks
#define NQ     (NCHK * 4)       // 8 kt-steps total per CTA
#define NPROB  16384
#define LSCALE 2048.0f    // 2^11 residual scale
#define LINV   (1.0f / 2048.0f)

// SMEM layout (dynamic): [0,32K) W tiles, [32K, 96K) x staging 4 bufs x 16KB
#define SM_W   0
#define SM_X   32768
#define XBUF   16384
#define SMEM_TOTAL (32768 + 4 * XBUF)

// partial scores [KSPL][TOK][NE] = 32 MB (L2-resident)
__device__ float g_part[KSPL * TOK * NE];
// W transposed + 2-level fp16 split (l pre-scaled by 2^11): [expert n][feature k]
__device__ __half g_Wh[NE * 2 * DD];
__device__ __half g_Wl[NE * 2 * DD];

// ---------------- helpers ----------------
__device__ __forceinline__ uint32_t smem_u32(const void* p) {
    uint32_t a;
    asm("{ .reg .u64 t; cvta.to.shared.u64 t, %1; cvt.u32.u64 %0, t; }" : "=r"(a) : "l"(p));
    return a;
}
__device__ __forceinline__ float fsqrt_ap(float x) {
    float r; asm("sqrt.approx.f32 %0, %1;" : "=f"(r) : "f"(x)); return r;
}
__device__ __forceinline__ uint32_t packh2(__half x, __half y) {
    __half2 v = __halves2half2(x, y);
    return *reinterpret_cast<uint32_t*>(&v);
}
// 2-level fp16 split of a float pair; l scaled by 2^11
__device__ __forceinline__ void split2h(float x, float y, uint32_t& h, uint32_t& l) {
    const __half hx = __float2half_rn(x);
    const __half hy = __float2half_rn(y);
    const float rx = (x - __half2float(hx)) * LSCALE;
    const float ry = (y - __half2float(hy)) * LSCALE;
    h = packh2(hx, hy);
    l = packh2(__float2half_rn(rx), __float2half_rn(ry));
}
__device__ __forceinline__ void mma16816(float* c, const uint32_t* a, const uint32_t* b) {
    asm volatile(
        "mma.sync.aligned.m16n8k16.row.col.f32.f16.f16.f32 "
        "{%0,%1,%2,%3}, {%4,%5,%6,%7}, {%8,%9}, {%0,%1,%2,%3};"
        : "+f"(c[0]), "+f"(c[1]), "+f"(c[2]), "+f"(c[3])
        : "r"(a[0]), "r"(a[1]), "r"(a[2]), "r"(a[3]), "r"(b[0]), "r"(b[1]));
}
__device__ __forceinline__ void ldsm4(uint32_t* r, uint32_t addr) {
    asm volatile("ldmatrix.sync.aligned.m8n8.x4.shared.b16 {%0,%1,%2,%3}, [%4];"
                 : "=r"(r[0]), "=r"(r[1]), "=r"(r[2]), "=r"(r[3]) : "r"(addr));
}
__device__ __forceinline__ void stsh128(uint32_t addr, uint4 v) {
    asm volatile("st.shared.v4.b32 [%0], {%1, %2, %3, %4};"
                 :: "r"(addr), "r"(v.x), "r"(v.y), "r"(v.z), "r"(v.w) : "memory");
}
__device__ __forceinline__ void cpa8(uint32_t dst, const float* src) {
    asm volatile("cp.async.ca.shared.global [%0], [%1], 8;" :: "r"(dst), "l"(src) : "memory");
}
__device__ __forceinline__ void cpa_commit() {
    asm volatile("cp.async.commit_group;" ::: "memory");
}
__device__ __forceinline__ float2 ldsf2(uint32_t a) {
    float2 v;
    asm volatile("ld.shared.v2.f32 {%0,%1}, [%2];" : "=f"(v.x), "=f"(v.y) : "r"(a));
    return v;
}

// ---------------- setup: transpose + 2-level fp16-split W ----------------
// 256 CTAs, each transposes a 16k x 64n tile (latency-parallel).
__global__ __launch_bounds__(256)
void wsplit_kernel(const float* __restrict__ W) {
    __shared__ float tile[16][65];
    const int k0  = blockIdx.x * 16;
    const int tid = threadIdx.x;
    {
        const int r  = tid >> 4;          // 0..15
        const int c4 = (tid & 15) * 4;    // 0..60
        const float4 v = *(const float4*)&W[(size_t)(k0 + r) * NE + c4];
        tile[r][c4]     = v.x;
        tile[r][c4 + 1] = v.y;
        tile[r][c4 + 2] = v.z;
        tile[r][c4 + 3] = v.w;
    }
    __syncthreads();
    const int n  = tid >> 2;          // 0..63
    const int ks = (tid & 3) * 4;     // 0,4,8,12
    union { __half h[4]; uint2 q; } hb, lb;
#pragma unroll
    for (int kk = 0; kk < 4; kk++) {
        const float v = tile[ks + kk][n];
        const __half h = __float2half_rn(v);
        hb.h[kk] = h;
        lb.h[kk] = __float2half_rn((v - __half2float(h)) * LSCALE);
    }
    const size_t idx = (size_t)n * (2 * DD) + k0 + ks;
    *(uint2*)(g_Wh + idx) = hb.q;
    *(uint2*)(g_Wl + idx) = lb.q;
}

// ---------------- main: fused amp/phase + 2-level fp16 split mma GEMM ----------------
// 8 warps, each owns m16 (16 tokens) x n64. A frags built in registers.
// x staged through smem via per-thread cp.async (zero register cost, no barriers).
__global__ __launch_bounds__(256, 2)
void gemm_mma_kernel(const float* __restrict__ xr, const float* __restrict__ xi) {
    extern __shared__ __align__(128) uint8_t smem[];
    const uint32_t swb = smem_u32(smem);          // W tiles at swb + SM_W
    const uint32_t sxb = swb + SM_X;              // x staging

    const int tid  = threadIdx.x;
    const int w    = tid >> 5;
    const int lane = tid & 31;
    const int qr   = lane >> 2;          // frag row 0..7
    const int qc   = (lane & 3) * 2;     // frag col pair
    const int tok0 = blockIdx.x * BM;
    const int ks   = blockIdx.y;

    // ldmatrix lane-address constants
    const uint32_t ldrow = ((lane >> 4) << 3) + (lane & 7);     // 0..15
    const uint32_t kboff = ((lane >> 3) & 1) * 16;              // 0 / 16 bytes
    const uint32_t kxor  = (lane & 7) << 4;                     // swizzle XOR

    float accm[8][4], accc[8][4];
#pragma unroll
    for (int nt = 0; nt < 8; nt++)
#pragma unroll
        for (int j = 0; j < 4; j++) { accm[nt][j] = 0.0f; accc[nt][j] = 0.0f; }

    const int rA = tok0 + w * 16 + qr;         // token row (and +8)
    const size_t rowbase = (size_t)rA * DD + qc + (size_t)ks * DSPL;
    const uint32_t sxt = sxb + (uint32_t)tid * 8;

    // issue kt-step q's 8 cp.async pieces into buffer q&3, as one group
    auto issue_q = [&](int q) {
        const uint32_t base = sxt + (uint32_t)(q & 3) * XBUF;
        const size_t b0 = rowbase + (size_t)q * 16;
        const size_t b1 = b0 + (size_t)8 * DD;
        cpa8(base + 0 * 2048, xr + b0);
        cpa8(base + 1 * 2048, xr + b0 + 8);
        cpa8(base + 2 * 2048, xr + b1);
        cpa8(base + 3 * 2048, xr + b1 + 8);
        cpa8(base + 4 * 2048, xi + b0);
        cpa8(base + 5 * 2048, xi + b0 + 8);
        cpa8(base + 6 * 2048, xi + b1);
        cpa8(base + 7 * 2048, xi + b1 + 8);
        cpa_commit();
    };

    // prologue: get 2 kt-steps in flight
    issue_q(0);
    issue_q(1);

    for (int c = 0; c < NCHK; c++) {
        const int koff = ks * DSPL + c * CHUNK;
        __syncthreads();
        // ---- stage W: 4 arrays, each thread moves 32B per array (swizzled smem)
        {
            const int n  = tid >> 2;
            const int ke = (tid & 3) * 16;
            const size_t gA = (size_t)n * (2 * DD) + koff + ke;
            const size_t gP = gA + DD;
            const uint32_t row = (uint32_t)n * 128;
            const uint32_t xv  = (uint32_t)(n & 7) << 4;
            const uint32_t c0  = row + (((uint32_t)(ke * 2)) ^ xv);
            const uint32_t c1  = row + (((uint32_t)(ke * 2 + 16)) ^ xv);
            uint4 v;
            v = *(const uint4*)(g_Wh + gA);     stsh128(swb + 0 * 8192 + c0, v);
            v = *(const uint4*)(g_Wh + gA + 8); stsh128(swb + 0 * 8192 + c1, v);
            v = *(const uint4*)(g_Wl + gA);     stsh128(swb + 1 * 8192 + c0, v);
            v = *(const uint4*)(g_Wl + gA + 8); stsh128(swb + 1 * 8192 + c1, v);
            v = *(const uint4*)(g_Wh + gP);     stsh128(swb + 2 * 8192 + c0, v);
            v = *(const uint4*)(g_Wh + gP + 8); stsh128(swb + 2 * 8192 + c1, v);
            v = *(const uint4*)(g_Wl + gP);     stsh128(swb + 3 * 8192 + c0, v);
            v = *(const uint4*)(g_Wl + gP + 8); stsh128(swb + 3 * 8192 + c1, v);
        }
        __syncthreads();

#pragma unroll
        for (int kt = 0; kt < 4; kt++) {
            const int q = c * 4 + kt;
            // ---- keep 2 kt-steps in flight
            if (q + 2 < NQ) issue_q(q + 2);
            // ---- wait for q's group
            if (q + 2 < NQ) {
                asm volatile("cp.async.wait_group 2;" ::: "memory");
            } else if (q + 1 < NQ) {
                asm volatile("cp.async.wait_group 1;" ::: "memory");
            } else {
                asm volatile("cp.async.wait_group 0;" ::: "memory");
            }

            // ---- read q's x from own staging slot (no barrier needed)
            const uint32_t rb = sxt + (uint32_t)(q & 3) * XBUF;
            const float2 r00 = ldsf2(rb + 0 * 2048);
            const float2 r02 = ldsf2(rb + 1 * 2048);
            const float2 r10 = ldsf2(rb + 2 * 2048);
            const float2 r12 = ldsf2(rb + 3 * 2048);
            const float2 i00 = ldsf2(rb + 4 * 2048);
            const float2 i02 = ldsf2(rb + 5 * 2048);
            const float2 i10 = ldsf2(rb + 6 * 2048);
            const float2 i12 = ldsf2(rb + 7 * 2048);

            // ---- amp (MUFU sqrt.approx, rel err ~2^-21) / phase (exact atan2f)
            const float a00 = fsqrt_ap(fmaf(r00.x, r00.x, i00.x * i00.x)), p00 = atan2f(i00.x, r00.x);
            const float a01 = fsqrt_ap(fmaf(r00.y, r00.y, i00.y * i00.y)), p01 = atan2f(i00.y, r00.y);
            const float a10 = fsqrt_ap(fmaf(r10.x, r10.x, i10.x * i10.x)), p10 = atan2f(i10.x, r10.x);
            const float a11 = fsqrt_ap(fmaf(r10.y, r10.y, i10.y * i10.y)), p11 = atan2f(i10.y, r10.y);
            const float a02 = fsqrt_ap(fmaf(r02.x, r02.x, i02.x * i02.x)), p02 = atan2f(i02.x, r02.x);
            const float a03 = fsqrt_ap(fmaf(r02.y, r02.y, i02.y * i02.y)), p03 = atan2f(i02.y, r02.y);
            const float a12 = fsqrt_ap(fmaf(r12.x, r12.x, i12.x * i12.x)), p12 = atan2f(i12.x, r12.x);
            const float a13 = fsqrt_ap(fmaf(r12.y, r12.y, i12.y * i12.y)), p13 = atan2f(i12.y, r12.y);

            // ---- 2-level fp16 split into A-fragment layout (l scaled 2^11)
            uint32_t Ah[4], Al[4], Ph[4], Pl[4];
            split2h(a00, a01, Ah[0], Al[0]);
            split2h(a10, a11, Ah[1], Al[1]);
            split2h(a02, a03, Ah[2], Al[2]);
            split2h(a12, a13, Ah[3], Al[3]);
            split2h(p00, p01, Ph[0], Pl[0]);
            split2h(p10, p11, Ph[1], Pl[1]);
            split2h(p02, p03, Ph[2], Pl[2]);
            split2h(p12, p13, Ph[3], Pl[3]);

            const uint32_t kb = ((uint32_t)(kt * 32) + kboff) ^ kxor;
            uint32_t wreg[16];

            // ---- amp Wh: main Ah*Wh, corr Al'*Wh
#pragma unroll
            for (int g = 0; g < 4; g++)
                ldsm4(&wreg[g * 4], swb + 0 * 8192 + (g * 16 + ldrow) * 128 + kb);
#pragma unroll
            for (int nt = 0; nt < 8; nt++) {
                mma16816(accm[nt], Ah, &wreg[nt * 2]);
                mma16816(accc[nt], Al, &wreg[nt * 2]);
            }
            // ---- amp Wl': corr Ah*Wl'
#pragma unroll
            for (int g = 0; g < 4; g++)
                ldsm4(&wreg[g * 4], swb + 1 * 8192 + (g * 16 + ldrow) * 128 + kb);
#pragma unroll
            for (int nt = 0; nt < 8; nt++)
                mma16816(accc[nt], Ah, &wreg[nt * 2]);

            // ---- phase Wh: main Ph*Wh, corr Pl'*Wh
#pragma unroll
            for (int g = 0; g < 4; g++)
                ldsm4(&wreg[g * 4], swb + 2 * 8192 + (g * 16 + ldrow) * 128 + kb);
#pragma unroll
            for (int nt = 0; nt < 8; nt++) {
                mma16816(accm[nt], Ph, &wreg[nt * 2]);
                mma16816(accc[nt], Pl, &wreg[nt * 2]);
            }
            // ---- phase Wl': corr Ph*Wl'
#pragma unroll
            for (int g = 0; g < 4; g++)
                ldsm4(&wreg[g * 4], swb + 3 * 8192 + (g * 16 + ldrow) * 128 + kb);
#pragma unroll
            for (int nt = 0; nt < 8; nt++)
                mma16816(accc[nt], Ph, &wreg[nt * 2]);
        }
    }

    // ---- epilogue: combine main + corr/2048, store to partials
    float* dst0 = g_part + ((size_t)ks * TOK + rA) * NE;
    float* dst1 = dst0 + (size_t)8 * NE;
#pragma unroll
    for (int nt = 0; nt < 8; nt++) {
        const float v0 = fmaf(accc[nt][0], LINV, accm[nt][0]);
        const float v1 = fmaf(accc[nt][1], LINV, accm[nt][1]);
        const float v2 = fmaf(accc[nt][2], LINV, accm[nt][2]);
        const float v3 = fmaf(accc[nt][3], LINV, accm[nt][3]);
        *(float2*)&dst0[nt * 8 + qc] = make_float2(v0, v1);
        *(float2*)&dst1[nt * 8 + qc] = make_float2(v2, v3);
    }
}

// ---------------- reduce + top-2 + renormalized softmax ----------------
__global__ __launch_bounds__(256)
void topk_kernel(const float* __restrict__ bvec, float* __restrict__ out) {
    const int gtid = blockIdx.x * blockDim.x + threadIdx.x;
    const int tok  = gtid >> 5;
    const int lane = threadIdx.x & 31;
    if (tok >= TOK) return;

    float s0 = 0.0f, s1 = 0.0f;
#pragma unroll
    for (int ks = 0; ks < KSPL; ks++) {
        const float2 v = *(const float2*)&g_part[((size_t)ks * TOK + tok) * NE + lane * 2];
        s0 += v.x; s1 += v.y;
    }
    s0 += bvec[2 * lane];
    s1 += bvec[2 * lane + 1];

    // top-1, jax tie-break (lower index wins on equal)
    float bv; int bi;
    if (s1 > s0) { bv = s1; bi = 2 * lane + 1; } else { bv = s0; bi = 2 * lane; }
#pragma unroll
    for (int off = 16; off > 0; off >>= 1) {
        const float ov = __shfl_down_sync(0xffffffffu, bv, off);
        const int   oi = __shfl_down_sync(0xffffffffu, bi, off);
        if (ov > bv || (ov == bv && oi < bi)) { bv = ov; bi = oi; }
    }
    bv = __shfl_sync(0xffffffffu, bv, 0);
    bi = __shfl_sync(0xffffffffu, bi, 0);

    const float NEG = -3.4e38f;
    float t0 = (2 * lane     == bi) ? NEG : s0;
    float t1 = (2 * lane + 1 == bi) ? NEG : s1;
    float cv; int ci;
    if (t1 > t0) { cv = t1; ci = 2 * lane + 1; } else { cv = t0; ci = 2 * lane; }
#pragma unroll
    for (int off = 16; off > 0; off >>= 1) {
        const float ov = __shfl_down_sync(0xffffffffu, cv, off);
        const int   oi = __shfl_down_sync(0xffffffffu, ci, off);
        if (ov > cv || (ov == cv && oi < ci)) { cv = ov; ci = oi; }
    }

    if (lane == 0) {
        // renormalized top-2 softmax: global denominator cancels, max = bv
        const float r  = expf(cv - bv);
        const float dn = 1.0f + r;
        out[tok * 2]             = 1.0f / dn;
        out[tok * 2 + 1]         = r / dn;
        out[NPROB + tok * 2]     = (float)bi;
        out[NPROB + tok * 2 + 1] = (float)ci;
    }
}

extern "C" void kernel_launch(void* const* d_in, const int* in_sizes, int n_in,
                              void* d_out, int out_size) {
    const float* xr = (const float*)d_in[0];   // x_real [4,2048,2048]
    const float* xi = (const float*)d_in[1];   // x_imag [4,2048,2048]
    const float* W  = (const float*)d_in[2];   // [4096, 64]
    const float* b  = (const float*)d_in[3];   // [64]
    float* out = (float*)d_out;                // [16384 probs][16384 indices]

    cudaFuncSetAttribute(gemm_mma_kernel, cudaFuncAttributeMaxDynamicSharedMemorySize, SMEM_TOTAL);

    wsplit_kernel<<<2 * DD / 16, 256>>>(W);
    dim3 grid(TOK / BM, KSPL);
    gemm_mma_kernel<<<grid, 256, SMEM_TOTAL>>>(xr, xi);
    topk_kernel<<<TOK * 32 / 256, 256>>>(b, out);
}